// round 15
// baseline (speedup 1.0000x reference)
#include <cuda_runtime.h>
#include <cstdint>

// Problem constants
#define T_LEN 256
#define S_N   32
#define C_IN  32
#define A_N   128
#define H_DIR 64
#define NB    32       // sequences (assets) per CTA
#define ZROWS 96       // C_IN + H_DIR rows of the per-step operand tile

// Shared memory layout (in floats)
#define WSM_SZ (96 * 256)   // transposed weights: wsm[c*256 + j], j = gate*64 + k
#define ZSM_SZ (96 * 32)    // zsm[row*32 + nb]; rows 0..31 = x_t, 32..95 = h
#define SMEM_FLOATS (WSM_SZ + ZSM_SZ)
#define SMEM_BYTES (SMEM_FLOATS * 4)   // 110592 B -> 2 CTAs/SM

// ---- packed fp32x2 helpers (Blackwell FFMA2: only reachable via PTX) ----
__device__ __forceinline__ unsigned long long pack2(float w) {
    unsigned long long r;
    unsigned int u = __float_as_uint(w);
    asm("mov.b64 %0, {%1, %1};" : "=l"(r) : "r"(u));
    return r;
}
__device__ __forceinline__ void fma2(unsigned long long& d,
                                     unsigned long long a,
                                     unsigned long long b) {
    asm("fma.rn.f32x2 %0, %1, %2, %0;" : "+l"(d) : "l"(a), "l"(b));
}
__device__ __forceinline__ float2 unpack2(unsigned long long v) {
    unsigned int lo, hi;
    asm("mov.b64 {%0, %1}, %2;" : "=r"(lo), "=r"(hi) : "l"(v));
    return make_float2(__uint_as_float(lo), __uint_as_float(hi));
}

// Fast, accurate-enough nonlinearities (__expf rel err ~1e-6)
__device__ __forceinline__ float sigf(float x) {
    return __fdividef(1.0f, 1.0f + __expf(-x));
}
__device__ __forceinline__ float tanhf_(float x) {
    return __fdividef(2.0f, 1.0f + __expf(-2.0f * x)) - 1.0f;
}

extern __shared__ float sm[];

__global__ __launch_bounds__(256, 2)
void lstm_bidir_kernel(const float* __restrict__ x,
                       const float* __restrict__ Wih_f,
                       const float* __restrict__ Whh_f,
                       const float* __restrict__ bih_f,
                       const float* __restrict__ bhh_f,
                       const float* __restrict__ Wih_b,
                       const float* __restrict__ Whh_b,
                       const float* __restrict__ bih_b,
                       const float* __restrict__ bhh_b,
                       float* __restrict__ out)
{
    float* wsm = sm;             // [c(96)][j(256)]
    float* zsm = sm + WSM_SZ;    // [row(96)][nb(32)]

    const int tid = threadIdx.x;
    const int bid = blockIdx.x;         // 0..255
    const int dir = bid >> 7;           // 0 = forward, 1 = backward
    const int b7  = bid & 127;
    const int s   = b7 >> 2;            // sample
    const int a0  = (b7 & 3) * NB;      // asset tile base

    const float* Wih = dir ? Wih_b : Wih_f;
    const float* Whh = dir ? Whh_b : Whh_f;
    const float* bih = dir ? bih_b : bih_f;
    const float* bhh = dir ? bhh_b : bhh_f;

    // ---- Load weights transposed into smem: wsm[c*256 + j] ----
    for (int idx = tid; idx < 256 * 32; idx += 256) {
        int j = idx >> 5, c = idx & 31;
        wsm[c * 256 + j] = Wih[idx];
    }
    for (int idx = tid; idx < 256 * 64; idx += 256) {
        int j = idx >> 6, kk = idx & 63;
        wsm[(32 + kk) * 256 + j] = Whh[idx];
    }
    // zero the h rows of the operand tile
    for (int idx = tid; idx < 64 * 32; idx += 256) zsm[32 * 32 + idx] = 0.0f;

    // Unified identity: this thread owns hidden unit k for 8 sequences nb0..nb0+7
    const int k   = tid >> 2;           // 0..63
    const int nb0 = (tid & 3) * 8;      // 0,8,16,24

    unsigned long long bb[4];
#pragma unroll
    for (int g = 0; g < 4; ++g)
        bb[g] = pack2(bih[g * 64 + k] + bhh[g * 64 + k]);

    // x-loader identity (coalesced 128B rows)
    const int nb_u = tid & 31;
    const int wq   = tid >> 5;

    float cst[8];
#pragma unroll
    for (int r = 0; r < 8; ++r) cst[r] = 0.0f;

    // Prologue: load x for the first timestep into zsm rows 0..31
    {
        const int tt0 = dir ? (T_LEN - 1) : 0;
        const float* xb = x + (((size_t)s * C_IN) * T_LEN + tt0) * A_N + a0;
#pragma unroll
        for (int q = 0; q < 4; ++q) {
            int c = q * 8 + wq;
            zsm[c * 32 + nb_u] = xb[(size_t)c * T_LEN * A_N + nb_u];
        }
    }
    __syncthreads();

    // out[s][dir*64 + k][t][a0 + nb0 .. +7]
    const size_t outRow =
        (((size_t)s * 128 + (dir ? H_DIR : 0) + k) * T_LEN) * A_N + a0 + nb0;

    unsigned long long acc[16];   // acc[g*4 + p]: gate g, nb pair p

    for (int t = 0; t < T_LEN; ++t) {
        const int tt = dir ? (T_LEN - 1 - t) : t;

        // ---- Gate GEMV: 4 gates x 8 sequences, all in registers ----
#pragma unroll
        for (int g = 0; g < 4; ++g)
#pragma unroll
            for (int p = 0; p < 4; ++p) acc[g * 4 + p] = bb[g];

#pragma unroll 2
        for (int c = 0; c < ZROWS; ++c) {
            const float* wrow = wsm + c * 256 + k;
            unsigned long long w0 = pack2(wrow[0]);
            unsigned long long w1 = pack2(wrow[64]);
            unsigned long long w2 = pack2(wrow[128]);
            unsigned long long w3 = pack2(wrow[192]);
            const ulonglong2* zr = (const ulonglong2*)(zsm + c * 32 + nb0);
            ulonglong2 za = zr[0];
            ulonglong2 zb = zr[1];
            fma2(acc[0],  w0, za.x); fma2(acc[1],  w0, za.y);
            fma2(acc[2],  w0, zb.x); fma2(acc[3],  w0, zb.y);
            fma2(acc[4],  w1, za.x); fma2(acc[5],  w1, za.y);
            fma2(acc[6],  w1, zb.x); fma2(acc[7],  w1, zb.y);
            fma2(acc[8],  w2, za.x); fma2(acc[9],  w2, za.y);
            fma2(acc[10], w2, zb.x); fma2(acc[11], w2, zb.y);
            fma2(acc[12], w3, za.x); fma2(acc[13], w3, za.y);
            fma2(acc[14], w3, zb.x); fma2(acc[15], w3, zb.y);
        }

        // prefetch next-step x before the barrier (global, independent of smem)
        const int ttn = dir ? (tt > 0 ? tt - 1 : 0)
                            : (tt < T_LEN - 1 ? tt + 1 : tt);
        float xpre[4];
        {
            const float* xb = x + (((size_t)s * C_IN) * T_LEN + ttn) * A_N + a0;
#pragma unroll
            for (int q = 0; q < 4; ++q) {
                int c = q * 8 + wq;
                xpre[q] = xb[(size_t)c * T_LEN * A_N + nb_u];
            }
        }

        __syncthreads();   // all zsm reads of this step complete

        // ---- State update: gates straight from registers ----
        float h_out[8];
#pragma unroll
        for (int p = 0; p < 4; ++p) {
            float2 gi = unpack2(acc[p]);
            float2 gf = unpack2(acc[4 + p]);
            float2 gg = unpack2(acc[8 + p]);
            float2 go = unpack2(acc[12 + p]);

            float cv = sigf(gf.x) * cst[2 * p] + sigf(gi.x) * tanhf_(gg.x);
            cst[2 * p] = cv;
            h_out[2 * p] = sigf(go.x) * tanhf_(cv);

            cv = sigf(gf.y) * cst[2 * p + 1] + sigf(gi.y) * tanhf_(gg.y);
            cst[2 * p + 1] = cv;
            h_out[2 * p + 1] = sigf(go.y) * tanhf_(cv);
        }

        // h -> zsm for next step (2x STS.128, conflict-free)
        float4* zh = (float4*)(zsm + (32 + k) * 32 + nb0);
        zh[0] = make_float4(h_out[0], h_out[1], h_out[2], h_out[3]);
        zh[1] = make_float4(h_out[4], h_out[5], h_out[6], h_out[7]);

        // output: 8 consecutive assets -> 2x STG.128, coalesced across sub-threads
        float4* og = (float4*)(out + outRow + (size_t)tt * A_N);
        og[0] = make_float4(h_out[0], h_out[1], h_out[2], h_out[3]);
        og[1] = make_float4(h_out[4], h_out[5], h_out[6], h_out[7]);

        // write the prefetched x for the next step
#pragma unroll
        for (int q = 0; q < 4; ++q)
            zsm[(q * 8 + wq) * 32 + nb_u] = xpre[q];

        __syncthreads();   // writes visible before next step's reads
    }
}

extern "C" void kernel_launch(void* const* d_in, const int* in_sizes, int n_in,
                              void* d_out, int out_size)
{
    (void)in_sizes; (void)n_in; (void)out_size;
    const float* x     = (const float*)d_in[0];
    const float* Wih_f = (const float*)d_in[1];
    const float* Whh_f = (const float*)d_in[2];
    const float* bih_f = (const float*)d_in[3];
    const float* bhh_f = (const float*)d_in[4];
    const float* Wih_b = (const float*)d_in[5];
    const float* Whh_b = (const float*)d_in[6];
    const float* bih_b = (const float*)d_in[7];
    const float* bhh_b = (const float*)d_in[8];
    float* out = (float*)d_out;

    cudaFuncSetAttribute(lstm_bidir_kernel,
                         cudaFuncAttributeMaxDynamicSharedMemorySize, SMEM_BYTES);

    // 256 CTAs: [0,128) forward, [128,256) backward; each owns (s, 32-asset tile)
    lstm_bidir_kernel<<<256, 256, SMEM_BYTES>>>(
        x, Wih_f, Whh_f, bih_f, bhh_f, Wih_b, Whh_b, bih_b, bhh_b, out);
}

// round 16
// speedup vs baseline: 1.0429x; 1.0429x over previous
#include <cuda_runtime.h>
#include <cstdint>

// Problem constants
#define T_LEN 256
#define S_N   32
#define C_IN  32
#define A_N   128
#define H_DIR 64
#define NB    32       // sequences (assets) per CTA
#define ZROWS 96       // C_IN + H_DIR rows of the per-step operand tile
#define NTHREADS 128

// Shared memory layout (in floats)
// wsm gate-interleaved: wsm[c*256 + k*4 + g]  (c: 0..31 input, 32..95 hidden)
#define WSM_SZ (96 * 256)
#define ZSM_SZ (96 * 32)    // zsm[row*32 + nb]; rows 0..31 = x_t, 32..95 = h
#define SMEM_FLOATS (WSM_SZ + ZSM_SZ)
#define SMEM_BYTES (SMEM_FLOATS * 4)   // 110592 B -> 2 CTAs/SM

// ---- packed fp32x2 helpers (Blackwell FFMA2: only reachable via PTX) ----
__device__ __forceinline__ unsigned long long pack2(float w) {
    unsigned long long r;
    unsigned int u = __float_as_uint(w);
    asm("mov.b64 %0, {%1, %1};" : "=l"(r) : "r"(u));
    return r;
}
__device__ __forceinline__ void fma2(unsigned long long& d,
                                     unsigned long long a,
                                     unsigned long long b) {
    asm("fma.rn.f32x2 %0, %1, %2, %0;" : "+l"(d) : "l"(a), "l"(b));
}
__device__ __forceinline__ float2 unpack2(unsigned long long v) {
    unsigned int lo, hi;
    asm("mov.b64 {%0, %1}, %2;" : "=r"(lo), "=r"(hi) : "l"(v));
    return make_float2(__uint_as_float(lo), __uint_as_float(hi));
}

// Fast, accurate-enough nonlinearities (__expf rel err ~1e-6)
__device__ __forceinline__ float sigf(float x) {
    return __fdividef(1.0f, 1.0f + __expf(-x));
}
__device__ __forceinline__ float tanhf_(float x) {
    return __fdividef(2.0f, 1.0f + __expf(-2.0f * x)) - 1.0f;
}

extern __shared__ float sm[];

__global__ __launch_bounds__(NTHREADS, 2)
void lstm_bidir_kernel(const float* __restrict__ x,
                       const float* __restrict__ Wih_f,
                       const float* __restrict__ Whh_f,
                       const float* __restrict__ bih_f,
                       const float* __restrict__ bhh_f,
                       const float* __restrict__ Wih_b,
                       const float* __restrict__ Whh_b,
                       const float* __restrict__ bih_b,
                       const float* __restrict__ bhh_b,
                       float* __restrict__ out)
{
    float* wsm = sm;             // [c(96)][k*4+g (256)]
    float* zsm = sm + WSM_SZ;    // [row(96)][nb(32)]

    const int tid = threadIdx.x;        // 0..127
    const int bid = blockIdx.x;         // 0..255
    const int dir = bid >> 7;           // 0 = forward, 1 = backward
    const int b7  = bid & 127;
    const int s   = b7 >> 2;            // sample
    const int a0  = (b7 & 3) * NB;      // asset tile base

    const float* Wih = dir ? Wih_b : Wih_f;
    const float* Whh = dir ? Whh_b : Whh_f;
    const float* bih = dir ? bih_b : bih_f;
    const float* bhh = dir ? bhh_b : bhh_f;

    // ---- Load weights into smem, gate-interleaved: wsm[c*256 + k*4 + g] ----
    // Wih: (256, 32) row-major (j=g*64+k, c)
    for (int idx = tid; idx < 256 * 32; idx += NTHREADS) {
        int j = idx >> 5, c = idx & 31;
        int g = j >> 6, k = j & 63;
        wsm[c * 256 + k * 4 + g] = Wih[idx];
    }
    // Whh: (256, 64) row-major (j, kk) -> rows 32..95
    for (int idx = tid; idx < 256 * 64; idx += NTHREADS) {
        int j = idx >> 6, kk = idx & 63;
        int g = j >> 6, k = j & 63;
        wsm[(32 + kk) * 256 + k * 4 + g] = Whh[idx];
    }
    // zero the h rows of the operand tile
    for (int idx = tid; idx < 64 * 32; idx += NTHREADS) zsm[32 * 32 + idx] = 0.0f;

    // Thread identity: 2 hidden units (k0, k0+1), 8 sequences nb0..nb0+7
    const int kt  = tid >> 2;           // 0..31
    const int k0  = kt * 2;             // even hidden unit
    const int nb0 = (tid & 3) * 8;      // 0,8,16,24

    // Packed biases: bb[k][g]
    unsigned long long bb[2][4];
#pragma unroll
    for (int kk = 0; kk < 2; ++kk)
#pragma unroll
        for (int g = 0; g < 4; ++g)
            bb[kk][g] = pack2(bih[g * 64 + k0 + kk] + bhh[g * 64 + k0 + kk]);

    // x-loader identity (coalesced 128B rows): 8 channels per thread
    const int nb_u = tid & 31;
    const int wq   = tid >> 5;          // 0..3

    float cst[16];
#pragma unroll
    for (int r = 0; r < 16; ++r) cst[r] = 0.0f;

    // Prologue: load x for the first timestep into zsm rows 0..31
    {
        const int tt0 = dir ? (T_LEN - 1) : 0;
        const float* xb = x + (((size_t)s * C_IN) * T_LEN + tt0) * A_N + a0;
#pragma unroll
        for (int q = 0; q < 8; ++q) {
            int c = q * 4 + wq;
            zsm[c * 32 + nb_u] = xb[(size_t)c * T_LEN * A_N + nb_u];
        }
    }
    __syncthreads();

    // out[s][dir*64 + k][t][a0 + nb0 .. +7]
    const size_t outRow0 =
        (((size_t)s * 128 + (dir ? H_DIR : 0) + k0) * T_LEN) * A_N + a0 + nb0;
    const size_t outRowStride = (size_t)T_LEN * A_N;   // +1 in k

    // acc[k*16 + g*4 + p]: unit k0+k, gate g, nb pair p
    unsigned long long acc[32];

    for (int t = 0; t < T_LEN; ++t) {
        const int tt = dir ? (T_LEN - 1 - t) : t;

        // ---- Gate GEMV: 2 units x 4 gates x 8 sequences, in registers ----
#pragma unroll
        for (int kk = 0; kk < 2; ++kk)
#pragma unroll
            for (int g = 0; g < 4; ++g)
#pragma unroll
                for (int p = 0; p < 4; ++p)
                    acc[kk * 16 + g * 4 + p] = bb[kk][g];

#pragma unroll 2
        for (int c = 0; c < ZROWS; ++c) {
            const float4* wr = (const float4*)(wsm + c * 256 + kt * 8);
            float4 wa = wr[0];   // unit k0:   gates i,f,g,o
            float4 wb = wr[1];   // unit k0+1: gates i,f,g,o
            const ulonglong2* zr = (const ulonglong2*)(zsm + c * 32 + nb0);
            ulonglong2 za = zr[0];
            ulonglong2 zb = zr[1];

            unsigned long long w;
            w = pack2(wa.x);
            fma2(acc[0],  w, za.x); fma2(acc[1],  w, za.y);
            fma2(acc[2],  w, zb.x); fma2(acc[3],  w, zb.y);
            w = pack2(wa.y);
            fma2(acc[4],  w, za.x); fma2(acc[5],  w, za.y);
            fma2(acc[6],  w, zb.x); fma2(acc[7],  w, zb.y);
            w = pack2(wa.z);
            fma2(acc[8],  w, za.x); fma2(acc[9],  w, za.y);
            fma2(acc[10], w, zb.x); fma2(acc[11], w, zb.y);
            w = pack2(wa.w);
            fma2(acc[12], w, za.x); fma2(acc[13], w, za.y);
            fma2(acc[14], w, zb.x); fma2(acc[15], w, zb.y);
            w = pack2(wb.x);
            fma2(acc[16], w, za.x); fma2(acc[17], w, za.y);
            fma2(acc[18], w, zb.x); fma2(acc[19], w, zb.y);
            w = pack2(wb.y);
            fma2(acc[20], w, za.x); fma2(acc[21], w, za.y);
            fma2(acc[22], w, zb.x); fma2(acc[23], w, zb.y);
            w = pack2(wb.z);
            fma2(acc[24], w, za.x); fma2(acc[25], w, za.y);
            fma2(acc[26], w, zb.x); fma2(acc[27], w, zb.y);
            w = pack2(wb.w);
            fma2(acc[28], w, za.x); fma2(acc[29], w, za.y);
            fma2(acc[30], w, zb.x); fma2(acc[31], w, zb.y);
        }

        // prefetch next-step x before the barrier (global, independent of smem)
        const int ttn = dir ? (tt > 0 ? tt - 1 : 0)
                            : (tt < T_LEN - 1 ? tt + 1 : tt);
        float xpre[8];
        {
            const float* xb = x + (((size_t)s * C_IN) * T_LEN + ttn) * A_N + a0;
#pragma unroll
            for (int q = 0; q < 8; ++q) {
                int c = q * 4 + wq;
                xpre[q] = xb[(size_t)c * T_LEN * A_N + nb_u];
            }
        }

        __syncthreads();   // all zsm reads of this step complete

        // ---- State update: gates straight from registers ----
#pragma unroll
        for (int kk = 0; kk < 2; ++kk) {
            float h_out[8];
#pragma unroll
            for (int p = 0; p < 4; ++p) {
                float2 gi = unpack2(acc[kk * 16 + p]);
                float2 gf = unpack2(acc[kk * 16 + 4 + p]);
                float2 gg = unpack2(acc[kk * 16 + 8 + p]);
                float2 go = unpack2(acc[kk * 16 + 12 + p]);

                int ci = kk * 8 + 2 * p;
                float cv = sigf(gf.x) * cst[ci] + sigf(gi.x) * tanhf_(gg.x);
                cst[ci] = cv;
                h_out[2 * p] = sigf(go.x) * tanhf_(cv);

                cv = sigf(gf.y) * cst[ci + 1] + sigf(gi.y) * tanhf_(gg.y);
                cst[ci + 1] = cv;
                h_out[2 * p + 1] = sigf(go.y) * tanhf_(cv);
            }

            // h -> zsm for next step (2x STS.128)
            float4* zh = (float4*)(zsm + (32 + k0 + kk) * 32 + nb0);
            zh[0] = make_float4(h_out[0], h_out[1], h_out[2], h_out[3]);
            zh[1] = make_float4(h_out[4], h_out[5], h_out[6], h_out[7]);

            // output: 8 consecutive assets -> 2x STG.128
            float4* og = (float4*)(out + outRow0 + kk * outRowStride
                                   + (size_t)tt * A_N);
            og[0] = make_float4(h_out[0], h_out[1], h_out[2], h_out[3]);
            og[1] = make_float4(h_out[4], h_out[5], h_out[6], h_out[7]);
        }

        // write the prefetched x for the next step
#pragma unroll
        for (int q = 0; q < 8; ++q)
            zsm[(q * 4 + wq) * 32 + nb_u] = xpre[q];

        __syncthreads();   // writes visible before next step's reads
    }
}

extern "C" void kernel_launch(void* const* d_in, const int* in_sizes, int n_in,
                              void* d_out, int out_size)
{
    (void)in_sizes; (void)n_in; (void)out_size;
    const float* x     = (const float*)d_in[0];
    const float* Wih_f = (const float*)d_in[1];
    const float* Whh_f = (const float*)d_in[2];
    const float* bih_f = (const float*)d_in[3];
    const float* bhh_f = (const float*)d_in[4];
    const float* Wih_b = (const float*)d_in[5];
    const float* Whh_b = (const float*)d_in[6];
    const float* bih_b = (const float*)d_in[7];
    const float* bhh_b = (const float*)d_in[8];
    float* out = (float*)d_out;

    cudaFuncSetAttribute(lstm_bidir_kernel,
                         cudaFuncAttributeMaxDynamicSharedMemorySize, SMEM_BYTES);

    // 256 CTAs: [0,128) forward, [128,256) backward; each owns (s, 32-asset tile)
    lstm_bidir_kernel<<<256, NTHREADS, SMEM_BYTES>>>(
        x, Wih_f, Whh_f, bih_f, bhh_f, Wih_b, Whh_b, bih_b, bhh_b, out);
}

// round 17
// speedup vs baseline: 1.1379x; 1.0911x over previous
#include <cuda_runtime.h>
#include <cstdint>

// Problem constants
#define T_LEN 256
#define S_N   32
#define C_IN  32
#define A_N   128
#define H_DIR 64
#define NB    32       // sequences (assets) per CTA
#define ZROWS 96       // C_IN + H_DIR rows of the per-step operand tile
#define NTHREADS 256

// Shared memory layout (in floats)
// wsm gate-interleaved: wsm[c*256 + k*4 + g]  (c: 0..31 input, 32..95 hidden)
#define WSM_SZ (96 * 256)
#define ZSM_SZ (96 * 32)    // zsm[row*32 + nb]; rows 0..31 = x_t, 32..95 = h
#define SMEM_FLOATS (WSM_SZ + ZSM_SZ)
#define SMEM_BYTES (SMEM_FLOATS * 4)   // 110592 B -> 2 CTAs/SM

// ---- packed fp32x2 helpers (Blackwell FFMA2: only reachable via PTX) ----
__device__ __forceinline__ unsigned long long pack2(float w) {
    unsigned long long r;
    unsigned int u = __float_as_uint(w);
    asm("mov.b64 %0, {%1, %1};" : "=l"(r) : "r"(u));
    return r;
}
__device__ __forceinline__ void fma2(unsigned long long& d,
                                     unsigned long long a,
                                     unsigned long long b) {
    asm("fma.rn.f32x2 %0, %1, %2, %0;" : "+l"(d) : "l"(a), "l"(b));
}
__device__ __forceinline__ float2 unpack2(unsigned long long v) {
    unsigned int lo, hi;
    asm("mov.b64 {%0, %1}, %2;" : "=r"(lo), "=r"(hi) : "l"(v));
    return make_float2(__uint_as_float(lo), __uint_as_float(hi));
}

// Fast, accurate-enough nonlinearities (__expf rel err ~1e-6)
__device__ __forceinline__ float sigf(float x) {
    return __fdividef(1.0f, 1.0f + __expf(-x));
}
__device__ __forceinline__ float tanhf_(float x) {
    return __fdividef(2.0f, 1.0f + __expf(-2.0f * x)) - 1.0f;
}

extern __shared__ float sm[];

__global__ __launch_bounds__(NTHREADS, 2)
void lstm_bidir_kernel(const float* __restrict__ x,
                       const float* __restrict__ Wih_f,
                       const float* __restrict__ Whh_f,
                       const float* __restrict__ bih_f,
                       const float* __restrict__ bhh_f,
                       const float* __restrict__ Wih_b,
                       const float* __restrict__ Whh_b,
                       const float* __restrict__ bih_b,
                       const float* __restrict__ bhh_b,
                       float* __restrict__ out)
{
    float* wsm = sm;             // [c(96)][k*4+g (256)]
    float* zsm = sm + WSM_SZ;    // [row(96)][nb(32)]

    const int tid = threadIdx.x;        // 0..255
    const int bid = blockIdx.x;         // 0..255
    const int dir = bid >> 7;           // 0 = forward, 1 = backward
    const int b7  = bid & 127;
    const int s   = b7 >> 2;            // sample
    const int a0  = (b7 & 3) * NB;      // asset tile base

    const float* Wih = dir ? Wih_b : Wih_f;
    const float* Whh = dir ? Whh_b : Whh_f;
    const float* bih = dir ? bih_b : bih_f;
    const float* bhh = dir ? bhh_b : bhh_f;

    // ---- Load weights into smem, gate-interleaved: wsm[c*256 + k*4 + g] ----
    // Wih: (256, 32) row-major (j=g*64+k, c)
    for (int idx = tid; idx < 256 * 32; idx += NTHREADS) {
        int j = idx >> 5, c = idx & 31;
        int g = j >> 6, kk = j & 63;
        wsm[c * 256 + kk * 4 + g] = Wih[idx];
    }
    // Whh: (256, 64) row-major (j, hk) -> rows 32..95
    for (int idx = tid; idx < 256 * 64; idx += NTHREADS) {
        int j = idx >> 6, hk = idx & 63;
        int g = j >> 6, kk = j & 63;
        wsm[(32 + hk) * 256 + kk * 4 + g] = Whh[idx];
    }
    // zero the h rows of the operand tile
    for (int idx = tid; idx < 64 * 32; idx += NTHREADS) zsm[32 * 32 + idx] = 0.0f;

    // Thread identity: hidden unit k, 8 sequences nb0..nb0+7
    const int k   = tid >> 2;           // 0..63
    const int nb0 = (tid & 3) * 8;      // 0,8,16,24

    // Packed biases per gate
    unsigned long long bb[4];
#pragma unroll
    for (int g = 0; g < 4; ++g)
        bb[g] = pack2(bih[g * 64 + k] + bhh[g * 64 + k]);

    // x-loader identity (coalesced 128B rows): 4 channels per thread
    const int nb_u = tid & 31;
    const int wq   = tid >> 5;          // 0..7

    float cst[8];
#pragma unroll
    for (int r = 0; r < 8; ++r) cst[r] = 0.0f;

    // Prologue: load x for the first timestep into zsm rows 0..31
    {
        const int tt0 = dir ? (T_LEN - 1) : 0;
        const float* xb = x + (((size_t)s * C_IN) * T_LEN + tt0) * A_N + a0;
#pragma unroll
        for (int q = 0; q < 4; ++q) {
            int c = q * 8 + wq;
            zsm[c * 32 + nb_u] = xb[(size_t)c * T_LEN * A_N + nb_u];
        }
    }
    __syncthreads();

    // out[s][dir*64 + k][t][a0 + nb0 .. +7]
    const size_t outRow =
        (((size_t)s * 128 + (dir ? H_DIR : 0) + k) * T_LEN) * A_N + a0 + nb0;

    // acc[g*4 + p]: gate g, nb pair p
    unsigned long long acc[16];

    for (int t = 0; t < T_LEN; ++t) {
        const int tt = dir ? (T_LEN - 1 - t) : t;

        // ---- Gate GEMV: 4 gates x 8 sequences, in registers ----
#pragma unroll
        for (int g = 0; g < 4; ++g)
#pragma unroll
            for (int p = 0; p < 4; ++p) acc[g * 4 + p] = bb[g];

#pragma unroll 4
        for (int c = 0; c < ZROWS; ++c) {
            float4 wa = *(const float4*)(wsm + c * 256 + k * 4);  // gates i,f,g,o
            const ulonglong2* zr = (const ulonglong2*)(zsm + c * 32 + nb0);
            ulonglong2 za = zr[0];
            ulonglong2 zb = zr[1];

            unsigned long long w;
            w = pack2(wa.x);
            fma2(acc[0],  w, za.x); fma2(acc[1],  w, za.y);
            fma2(acc[2],  w, zb.x); fma2(acc[3],  w, zb.y);
            w = pack2(wa.y);
            fma2(acc[4],  w, za.x); fma2(acc[5],  w, za.y);
            fma2(acc[6],  w, zb.x); fma2(acc[7],  w, zb.y);
            w = pack2(wa.z);
            fma2(acc[8],  w, za.x); fma2(acc[9],  w, za.y);
            fma2(acc[10], w, zb.x); fma2(acc[11], w, zb.y);
            w = pack2(wa.w);
            fma2(acc[12], w, za.x); fma2(acc[13], w, za.y);
            fma2(acc[14], w, zb.x); fma2(acc[15], w, zb.y);
        }

        // prefetch next-step x before the barrier (global, independent of smem)
        const int ttn = dir ? (tt > 0 ? tt - 1 : 0)
                            : (tt < T_LEN - 1 ? tt + 1 : tt);
        float xpre[4];
        {
            const float* xb = x + (((size_t)s * C_IN) * T_LEN + ttn) * A_N + a0;
#pragma unroll
            for (int q = 0; q < 4; ++q) {
                int c = q * 8 + wq;
                xpre[q] = xb[(size_t)c * T_LEN * A_N + nb_u];
            }
        }

        __syncthreads();   // all zsm reads of this step complete

        // ---- State update: gates straight from registers ----
        float h_out[8];
#pragma unroll
        for (int p = 0; p < 4; ++p) {
            float2 gi = unpack2(acc[p]);
            float2 gf = unpack2(acc[4 + p]);
            float2 gg = unpack2(acc[8 + p]);
            float2 go = unpack2(acc[12 + p]);

            float cv = sigf(gf.x) * cst[2 * p] + sigf(gi.x) * tanhf_(gg.x);
            cst[2 * p] = cv;
            h_out[2 * p] = sigf(go.x) * tanhf_(cv);

            cv = sigf(gf.y) * cst[2 * p + 1] + sigf(gi.y) * tanhf_(gg.y);
            cst[2 * p + 1] = cv;
            h_out[2 * p + 1] = sigf(go.y) * tanhf_(cv);
        }

        // h -> zsm for next step (2x STS.128, conflict-free)
        float4* zh = (float4*)(zsm + (32 + k) * 32 + nb0);
        zh[0] = make_float4(h_out[0], h_out[1], h_out[2], h_out[3]);
        zh[1] = make_float4(h_out[4], h_out[5], h_out[6], h_out[7]);

        // output: 8 consecutive assets -> 2x STG.128, coalesced
        float4* og = (float4*)(out + outRow + (size_t)tt * A_N);
        og[0] = make_float4(h_out[0], h_out[1], h_out[2], h_out[3]);
        og[1] = make_float4(h_out[4], h_out[5], h_out[6], h_out[7]);

        // write the prefetched x for the next step
#pragma unroll
        for (int q = 0; q < 4; ++q)
            zsm[(q * 8 + wq) * 32 + nb_u] = xpre[q];

        __syncthreads();   // writes visible before next step's reads
    }
}

extern "C" void kernel_launch(void* const* d_in, const int* in_sizes, int n_in,
                              void* d_out, int out_size)
{
    (void)in_sizes; (void)n_in; (void)out_size;
    const float* x     = (const float*)d_in[0];
    const float* Wih_f = (const float*)d_in[1];
    const float* Whh_f = (const float*)d_in[2];
    const float* bih_f = (const float*)d_in[3];
    const float* bhh_f = (const float*)d_in[4];
    const float* Wih_b = (const float*)d_in[5];
    const float* Whh_b = (const float*)d_in[6];
    const float* bih_b = (const float*)d_in[7];
    const float* bhh_b = (const float*)d_in[8];
    float* out = (float*)d_out;

    cudaFuncSetAttribute(lstm_bidir_kernel,
                         cudaFuncAttributeMaxDynamicSharedMemorySize, SMEM_BYTES);

    // 256 CTAs: [0,128) forward, [128,256) backward; each owns (s, 32-asset tile)
    lstm_bidir_kernel<<<256, NTHREADS, SMEM_BYTES>>>(
        x, Wih_f, Whh_f, bih_f, bhh_f, Wih_b, Whh_b, bih_b, bhh_b, out);
}